// round 16
// baseline (speedup 1.0000x reference)
#include <cuda_runtime.h>
#include <math.h>

// Problem constants
#define NN   100000
#define EE   800000
#define EHH  400000

// ---------------------------------------------------------------------------
// Scratch (no allocations allowed -> __device__ globals)
// ---------------------------------------------------------------------------
__device__ float g_v    [(size_t)NN * 128];   // scatter result v
__device__ float g_vhull[(size_t)NN * 128];   // v @ w_hull, later reused for silu(out_hull@w1)
__device__ float g_acc  [(size_t)NN * 128];   // hull scatter accumulator, later reused for v2
__device__ float g_buf1 [(size_t)NN * 256];
__device__ float g_buf2 [(size_t)NN * 256];

// ---------------------------------------------------------------------------
// Helpers
// ---------------------------------------------------------------------------
__device__ __forceinline__ void red_add_v4(float* addr, float4 v) {
    asm volatile("red.global.add.v4.f32 [%0], {%1,%2,%3,%4};"
                 :: "l"(addr), "f"(v.x), "f"(v.y), "f"(v.z), "f"(v.w)
                 : "memory");
}

__device__ __forceinline__ float silu_f(float x) { return x / (1.0f + expf(-x)); }

// ---------------------------------------------------------------------------
// Zero two buffers
// ---------------------------------------------------------------------------
__global__ void zero2_kernel(float4* __restrict__ a, float4* __restrict__ b, int n4) {
    const float4 z = make_float4(0.f, 0.f, 0.f, 0.f);
    const int stride = gridDim.x * blockDim.x;
    for (int i = blockIdx.x * blockDim.x + threadIdx.x; i < n4; i += stride) {
        a[i] = z;
        b[i] = z;
    }
}

// ---------------------------------------------------------------------------
// K1: v = segment_sum(e2, i)   (32 threads per edge row, float4 vector atomics)
// ---------------------------------------------------------------------------
__global__ void scatter_kernel(const float* __restrict__ e2, const int* __restrict__ idx,
                               float* __restrict__ v, int E) {
    int t = blockIdx.x * blockDim.x + threadIdx.x;
    int e = t >> 5;
    if (e >= E) return;
    int c = (t & 31) << 2;
    float4 val = *reinterpret_cast<const float4*>(e2 + (size_t)e * 128 + c);
    int node = __ldg(idx + e);
    red_add_v4(v + (size_t)node * 128 + c, val);
}

// ---------------------------------------------------------------------------
// Generic fp32 GEMM: C[M,NOUT_tile] = [A1 | A2] @ W (+bias) (silu?)
// A1: [M,K1] row-major, A2: [M,K2] row-major (may be null), W: [K1+K2, NOUT]
// Block tile 128x128, BK=8, 256 threads, 8x8 micro-tile per thread.
// ---------------------------------------------------------------------------
template <bool BIAS, bool SILU>
__global__ __launch_bounds__(256)
void sgemm_kernel(const float* __restrict__ A1, int K1,
                  const float* __restrict__ A2, int K2,
                  const float* __restrict__ W, const float* __restrict__ bias,
                  float* __restrict__ C, int M, int NOUT) {
    __shared__ float As[8][128];   // transposed: As[k][row]
    __shared__ float Bs[8][128];   // Bs[k][col]

    const int K = K1 + K2;
    const int tid = threadIdx.x;
    const int tx = tid & 15;
    const int ty = tid >> 4;
    const int rowBase = blockIdx.x * 128;
    const int colBase = blockIdx.y * 128;

    const int arow = tid >> 1;         // 0..127
    const int acol = (tid & 1) * 4;    // 0 or 4
    const int am   = rowBase + arow;
    const int bk   = tid >> 5;         // 0..7
    const int bn   = (tid & 31) * 4;   // 0..124

    float acc[8][8];
#pragma unroll
    for (int i = 0; i < 8; i++)
#pragma unroll
        for (int j = 0; j < 8; j++) acc[i][j] = 0.f;

    for (int k0 = 0; k0 < K; k0 += 8) {
        float4 av = make_float4(0.f, 0.f, 0.f, 0.f);
        if (am < M) {
            int k = k0 + acol;
            if (k < K1) av = *reinterpret_cast<const float4*>(A1 + (size_t)am * K1 + k);
            else        av = *reinterpret_cast<const float4*>(A2 + (size_t)am * K2 + (k - K1));
        }
        float4 bv = *reinterpret_cast<const float4*>(W + (size_t)(k0 + bk) * NOUT + colBase + bn);

        __syncthreads();
        As[acol + 0][arow] = av.x;
        As[acol + 1][arow] = av.y;
        As[acol + 2][arow] = av.z;
        As[acol + 3][arow] = av.w;
        *reinterpret_cast<float4*>(&Bs[bk][bn]) = bv;
        __syncthreads();

#pragma unroll
        for (int kk = 0; kk < 8; kk++) {
            float a[8], b[8];
            *reinterpret_cast<float4*>(&a[0]) = *reinterpret_cast<const float4*>(&As[kk][ty * 8]);
            *reinterpret_cast<float4*>(&a[4]) = *reinterpret_cast<const float4*>(&As[kk][ty * 8 + 4]);
            *reinterpret_cast<float4*>(&b[0]) = *reinterpret_cast<const float4*>(&Bs[kk][tx * 8]);
            *reinterpret_cast<float4*>(&b[4]) = *reinterpret_cast<const float4*>(&Bs[kk][tx * 8 + 4]);
#pragma unroll
            for (int i = 0; i < 8; i++)
#pragma unroll
                for (int j = 0; j < 8; j++) acc[i][j] = fmaf(a[i], b[j], acc[i][j]);
        }
    }

    float bl[8];
#pragma unroll
    for (int j = 0; j < 8; j++) bl[j] = BIAS ? bias[colBase + tx * 8 + j] : 0.f;

#pragma unroll
    for (int i = 0; i < 8; i++) {
        int m = rowBase + ty * 8 + i;
        if (m >= M) continue;
        float r[8];
#pragma unroll
        for (int j = 0; j < 8; j++) {
            float x = acc[i][j] + bl[j];
            r[j] = SILU ? silu_f(x) : x;
        }
        float* cp = C + (size_t)m * NOUT + colBase + tx * 8;
        *reinterpret_cast<float4*>(cp)     = *reinterpret_cast<float4*>(&r[0]);
        *reinterpret_cast<float4*>(cp + 4) = *reinterpret_cast<float4*>(&r[4]);
    }
}

// ---------------------------------------------------------------------------
// Fused hull-edge kernel. Per block: 128 hull edges.
//   H   = silu(fea[128,16] @ W0 + b0)           (GEMM1, K=16, H kept in smem)
//   Wh  = H @ W1 + b1                           (GEMM2, K=128, BK=8 streamed)
//   e   = v_hull[j] * Wh ; red.add into acc[i]  (gather-multiply-scatter)
// Dynamic smem ~90KB -> 2 CTAs/SM.
// ---------------------------------------------------------------------------
__global__ __launch_bounds__(256, 2)
void hull_kernel(const float* __restrict__ fea, const int* __restrict__ jidx,
                 const int* __restrict__ iidx,
                 const float* __restrict__ W0, const float* __restrict__ b0,
                 const float* __restrict__ W1, const float* __restrict__ b1,
                 const float* __restrict__ vhull, float* __restrict__ accv, int EH) {
    extern __shared__ float sm[];
    float* sFeaT = sm;                  // [16][128] transposed fea tile
    float* sW0   = sFeaT + 16 * 128;    // [16][128]
    float* sH    = sW0 + 16 * 128;      // [128][132] (padded rows)
    float* sW1   = sH + 128 * 132;      // [8][128]
    float* sB0   = sW1 + 8 * 128;       // [128]
    float* sB1   = sB0 + 128;           // [128]
    int*   sJ    = (int*)(sB1 + 128);   // [128]
    int*   sI    = sJ + 128;            // [128]

    const int tid = threadIdx.x;
    const int tx = tid & 15;
    const int ty = tid >> 4;
    const int ebase = blockIdx.x * 128;

    // Load fea tile transposed: 512 float4, 2 per thread
#pragma unroll
    for (int q = 0; q < 2; q++) {
        int idx = tid * 2 + q;          // 0..511
        int row = idx >> 2;             // 0..127
        int kk = (idx & 3) * 4;         // 0,4,8,12
        int e = ebase + row;
        float4 f = make_float4(0.f, 0.f, 0.f, 0.f);
        if (e < EH) f = *reinterpret_cast<const float4*>(fea + (size_t)e * 16 + kk);
        sFeaT[(kk + 0) * 128 + row] = f.x;
        sFeaT[(kk + 1) * 128 + row] = f.y;
        sFeaT[(kk + 2) * 128 + row] = f.z;
        sFeaT[(kk + 3) * 128 + row] = f.w;
    }
    // Load W0 [16,128]
#pragma unroll
    for (int q = 0; q < 2; q++) {
        int idx = tid * 2 + q;          // 0..511
        int k = idx >> 5;               // 0..15
        int n = (idx & 31) * 4;
        *reinterpret_cast<float4*>(&sW0[k * 128 + n]) =
            *reinterpret_cast<const float4*>(W0 + (size_t)k * 128 + n);
    }
    if (tid < 128) {
        sB0[tid] = b0[tid];
        sB1[tid] = b1[tid];
        int e = ebase + tid;
        sJ[tid] = (e < EH) ? jidx[e] : 0;
        sI[tid] = (e < EH) ? iidx[e] : 0;
    }
    __syncthreads();

    float acc[8][8];
#pragma unroll
    for (int i = 0; i < 8; i++)
#pragma unroll
        for (int j = 0; j < 8; j++) acc[i][j] = 0.f;

    // GEMM1: K = 16
#pragma unroll
    for (int kk = 0; kk < 16; kk++) {
        float a[8], b[8];
        *reinterpret_cast<float4*>(&a[0]) = *reinterpret_cast<const float4*>(&sFeaT[kk * 128 + ty * 8]);
        *reinterpret_cast<float4*>(&a[4]) = *reinterpret_cast<const float4*>(&sFeaT[kk * 128 + ty * 8 + 4]);
        *reinterpret_cast<float4*>(&b[0]) = *reinterpret_cast<const float4*>(&sW0[kk * 128 + tx * 8]);
        *reinterpret_cast<float4*>(&b[4]) = *reinterpret_cast<const float4*>(&sW0[kk * 128 + tx * 8 + 4]);
#pragma unroll
        for (int i = 0; i < 8; i++)
#pragma unroll
            for (int j = 0; j < 8; j++) acc[i][j] = fmaf(a[i], b[j], acc[i][j]);
    }

    // SiLU + bias0 -> H (row-major, padded stride 132)
#pragma unroll
    for (int i = 0; i < 8; i++) {
        int row = ty * 8 + i;
        float r[8];
#pragma unroll
        for (int j = 0; j < 8; j++) r[j] = silu_f(acc[i][j] + sB0[tx * 8 + j]);
        *reinterpret_cast<float4*>(&sH[row * 132 + tx * 8])     = *reinterpret_cast<float4*>(&r[0]);
        *reinterpret_cast<float4*>(&sH[row * 132 + tx * 8 + 4]) = *reinterpret_cast<float4*>(&r[4]);
    }
    __syncthreads();

    // GEMM2: Wh = H @ W1, K = 128, BK = 8 streamed
#pragma unroll
    for (int i = 0; i < 8; i++)
#pragma unroll
        for (int j = 0; j < 8; j++) acc[i][j] = 0.f;

    for (int k0 = 0; k0 < 128; k0 += 8) {
        float4 wv = *reinterpret_cast<const float4*>(W1 + (size_t)(k0 + (tid >> 5)) * 128 + (tid & 31) * 4);
        __syncthreads();
        *reinterpret_cast<float4*>(&sW1[(tid >> 5) * 128 + (tid & 31) * 4]) = wv;
        __syncthreads();
#pragma unroll
        for (int kk = 0; kk < 8; kk++) {
            float a[8], b[8];
#pragma unroll
            for (int i = 0; i < 8; i++) a[i] = sH[(ty * 8 + i) * 132 + k0 + kk];
            *reinterpret_cast<float4*>(&b[0]) = *reinterpret_cast<const float4*>(&sW1[kk * 128 + tx * 8]);
            *reinterpret_cast<float4*>(&b[4]) = *reinterpret_cast<const float4*>(&sW1[kk * 128 + tx * 8 + 4]);
#pragma unroll
            for (int i = 0; i < 8; i++)
#pragma unroll
                for (int j = 0; j < 8; j++) acc[i][j] = fmaf(a[i], b[j], acc[i][j]);
        }
    }

    // Epilogue: bias1, multiply by gathered v_hull[j], vector-atomic scatter to acc[i]
    float bl[8];
#pragma unroll
    for (int j = 0; j < 8; j++) bl[j] = sB1[tx * 8 + j];

#pragma unroll
    for (int i = 0; i < 8; i++) {
        int e = ebase + ty * 8 + i;
        if (e >= EH) continue;
        int jn = sJ[ty * 8 + i];
        int in_ = sI[ty * 8 + i];
        const float* vr = vhull + (size_t)jn * 128 + tx * 8;
        float4 v0 = *reinterpret_cast<const float4*>(vr);
        float4 v1 = *reinterpret_cast<const float4*>(vr + 4);
        float4 r0, r1;
        r0.x = (acc[i][0] + bl[0]) * v0.x;
        r0.y = (acc[i][1] + bl[1]) * v0.y;
        r0.z = (acc[i][2] + bl[2]) * v0.z;
        r0.w = (acc[i][3] + bl[3]) * v0.w;
        r1.x = (acc[i][4] + bl[4]) * v1.x;
        r1.y = (acc[i][5] + bl[5]) * v1.y;
        r1.z = (acc[i][6] + bl[6]) * v1.z;
        r1.w = (acc[i][7] + bl[7]) * v1.w;
        float* op = accv + (size_t)in_ * 128 + tx * 8;
        red_add_v4(op, r0);
        red_add_v4(op + 4, r1);
    }
}

// ---------------------------------------------------------------------------
// Final projection: out[m] = dot(T[m, :256], w_out)   (one warp per row)
// ---------------------------------------------------------------------------
__global__ void dot_kernel(const float* __restrict__ T, const float* __restrict__ w,
                           float* __restrict__ out, int M) {
    int gw = (blockIdx.x * blockDim.x + threadIdx.x) >> 5;
    int lane = threadIdx.x & 31;
    if (gw >= M) return;
    const float4* row = reinterpret_cast<const float4*>(T + (size_t)gw * 256);
    const float4* wr  = reinterpret_cast<const float4*>(w);
    float4 a = row[lane];
    float4 b = row[lane + 32];
    float4 wa = __ldg(&wr[lane]);
    float4 wb = __ldg(&wr[lane + 32]);
    float s = a.x * wa.x + a.y * wa.y + a.z * wa.z + a.w * wa.w
            + b.x * wb.x + b.y * wb.y + b.z * wb.z + b.w * wb.w;
#pragma unroll
    for (int o = 16; o; o >>= 1) s += __shfl_down_sync(0xffffffffu, s, o);
    if (lane == 0) out[gw] = s;
}

// ---------------------------------------------------------------------------
// Launch
// ---------------------------------------------------------------------------
extern "C" void kernel_launch(void* const* d_in, const int* in_sizes, int n_in,
                              void* d_out, int out_size) {
    const float* e2      = (const float*)d_in[0];
    const int*   iidx    = (const int*)d_in[1];
    const float* fea     = (const float*)d_in[2];
    const int*   eih     = (const int*)d_in[3];    // [2, EH]: row0 = j_, row1 = i_
    const float* w_hull  = (const float*)d_in[4];
    const float* w_mlp0  = (const float*)d_in[5];
    const float* b_mlp0  = (const float*)d_in[6];
    const float* w_mlp1  = (const float*)d_in[7];
    const float* b_mlp1  = (const float*)d_in[8];
    const float* w1_hull = (const float*)d_in[9];
    const float* b1_hull = (const float*)d_in[10];
    const float* w2_hull = (const float*)d_in[11];
    const float* b2_hull = (const float*)d_in[12];
    const float* w_cat   = (const float*)d_in[13];
    const float* b_cat   = (const float*)d_in[14];
    const float* w_up    = (const float*)d_in[15];
    const float* b_up    = (const float*)d_in[16];
    const float* w_l0    = (const float*)d_in[17];
    const float* b_l0    = (const float*)d_in[18];
    const float* w_l1    = (const float*)d_in[19];
    const float* b_l1    = (const float*)d_in[20];
    const float* w_out   = (const float*)d_in[21];
    float* out = (float*)d_out;

    float *pv, *pvh, *pacc, *pb1, *pb2;
    cudaGetSymbolAddress((void**)&pv,   g_v);
    cudaGetSymbolAddress((void**)&pvh,  g_vhull);
    cudaGetSymbolAddress((void**)&pacc, g_acc);
    cudaGetSymbolAddress((void**)&pb1,  g_buf1);
    cudaGetSymbolAddress((void**)&pb2,  g_buf2);

    const int hull_smem = (16 * 128 + 16 * 128 + 128 * 132 + 8 * 128 + 128 + 128 + 128 + 128) * 4;
    cudaFuncSetAttribute(hull_kernel, cudaFuncAttributeMaxDynamicSharedMemorySize, hull_smem);

    // 0: zero v and the hull accumulator
    zero2_kernel<<<2048, 256>>>((float4*)pv, (float4*)pacc, NN * 128 / 4);

    // 1: v = segment_sum(e2, i)
    scatter_kernel<<<(EE * 32 + 255) / 256, 256>>>(e2, iidx, pv, EE);

    dim3 g1((NN + 127) / 128, 1);
    dim3 g2((NN + 127) / 128, 2);

    // 2: v_hull = v @ w_hull
    sgemm_kernel<false, false><<<g1, 256>>>(pv, 128, nullptr, 0, w_hull, nullptr, pvh, NN, 128);

    // 3: fused hull-edge MLP + gather-multiply + scatter-sum -> g_acc
    hull_kernel<<<(EHH + 127) / 128, 256, hull_smem>>>(
        fea, eih, eih + EHH, w_mlp0, b_mlp0, w_mlp1, b_mlp1, pvh, pacc, EHH);

    // 4: oh1 = silu(g_acc @ w1_hull + b1)          -> reuse g_vhull
    sgemm_kernel<true, true><<<g1, 256>>>(pacc, 128, nullptr, 0, w1_hull, b1_hull, pvh, NN, 128);

    // 5: oh2 = oh1 @ w2_hull + b2  [N,256]         -> g_buf1
    sgemm_kernel<true, false><<<g2, 256>>>(pvh, 128, nullptr, 0, w2_hull, b2_hull, pb1, NN, 256);

    // 6: v2 = silu(concat(v, oh2) @ w_cat + b)     -> reuse g_acc (split-A GEMM, K=128+256)
    sgemm_kernel<true, true><<<g1, 256>>>(pv, 128, pb1, 256, w_cat, b_cat, pacc, NN, 128);

    // 7: t = v2 @ w_up + b                          -> g_buf2
    sgemm_kernel<true, false><<<g2, 256>>>(pacc, 128, nullptr, 0, w_up, b_up, pb2, NN, 256);

    // 8: t = silu(t @ w_l0 + b)                     -> g_buf1
    sgemm_kernel<true, true><<<g2, 256>>>(pb2, 256, nullptr, 0, w_l0, b_l0, pb1, NN, 256);

    // 9: t = silu(t @ w_l1 + b)                     -> g_buf2
    sgemm_kernel<true, true><<<g2, 256>>>(pb1, 256, nullptr, 0, w_l1, b_l1, pb2, NN, 256);

    // 10: out = t @ w_out
    dot_kernel<<<(NN * 32 + 255) / 256, 256>>>(pb2, w_out, out, NN);
}

// round 17
// speedup vs baseline: 1.0010x; 1.0010x over previous
#include <cuda_runtime.h>
#include <math.h>

// Problem constants
#define NN   100000
#define EE   800000
#define EHH  400000

// ---------------------------------------------------------------------------
// Scratch (no allocations allowed -> __device__ globals)
// ---------------------------------------------------------------------------
__device__ float g_v    [(size_t)NN * 128];   // scatter result v
__device__ float g_vhull[(size_t)NN * 128];   // v @ w_hull, later reused for silu(out_hull@w1)
__device__ float g_acc  [(size_t)NN * 128];   // hull scatter accumulator, later reused for v2
__device__ float g_buf1 [(size_t)NN * 256];
__device__ float g_buf2 [(size_t)NN * 256];

// ---------------------------------------------------------------------------
// Helpers
// ---------------------------------------------------------------------------
__device__ __forceinline__ void red_add_v4(float* addr, float4 v) {
    asm volatile("red.global.add.v4.f32 [%0], {%1,%2,%3,%4};"
                 :: "l"(addr), "f"(v.x), "f"(v.y), "f"(v.z), "f"(v.w)
                 : "memory");
}

__device__ __forceinline__ float silu_f(float x) { return x / (1.0f + expf(-x)); }

// ---------------------------------------------------------------------------
// Zero two buffers
// ---------------------------------------------------------------------------
__global__ void zero2_kernel(float4* __restrict__ a, float4* __restrict__ b, int n4) {
    const float4 z = make_float4(0.f, 0.f, 0.f, 0.f);
    const int stride = gridDim.x * blockDim.x;
    for (int i = blockIdx.x * blockDim.x + threadIdx.x; i < n4; i += stride) {
        a[i] = z;
        b[i] = z;
    }
}

// ---------------------------------------------------------------------------
// K1: v = segment_sum(e2, i)   (32 threads per edge row, float4 vector atomics)
// ---------------------------------------------------------------------------
__global__ void scatter_kernel(const float* __restrict__ e2, const int* __restrict__ idx,
                               float* __restrict__ v, int E) {
    int t = blockIdx.x * blockDim.x + threadIdx.x;
    int e = t >> 5;
    if (e >= E) return;
    int c = (t & 31) << 2;
    float4 val = *reinterpret_cast<const float4*>(e2 + (size_t)e * 128 + c);
    int node = __ldg(idx + e);
    red_add_v4(v + (size_t)node * 128 + c, val);
}

// ---------------------------------------------------------------------------
// Generic fp32 GEMM: C[M,NOUT_tile] = [A1 | A2] @ W (+bias) (silu?)
// A1: [M,K1] row-major, A2: [M,K2] row-major (may be null), W: [K1+K2, NOUT]
// Block tile 128x128, BK=8, 256 threads, 8x8 micro-tile per thread.
// ---------------------------------------------------------------------------
template <bool BIAS, bool SILU>
__global__ __launch_bounds__(256)
void sgemm_kernel(const float* __restrict__ A1, int K1,
                  const float* __restrict__ A2, int K2,
                  const float* __restrict__ W, const float* __restrict__ bias,
                  float* __restrict__ C, int M, int NOUT) {
    __shared__ float As[8][128];   // transposed: As[k][row]
    __shared__ float Bs[8][128];   // Bs[k][col]

    const int K = K1 + K2;
    const int tid = threadIdx.x;
    const int tx = tid & 15;
    const int ty = tid >> 4;
    const int rowBase = blockIdx.x * 128;
    const int colBase = blockIdx.y * 128;

    const int arow = tid >> 1;         // 0..127
    const int acol = (tid & 1) * 4;    // 0 or 4
    const int am   = rowBase + arow;
    const int bk   = tid >> 5;         // 0..7
    const int bn   = (tid & 31) * 4;   // 0..124

    float acc[8][8];
#pragma unroll
    for (int i = 0; i < 8; i++)
#pragma unroll
        for (int j = 0; j < 8; j++) acc[i][j] = 0.f;

    for (int k0 = 0; k0 < K; k0 += 8) {
        float4 av = make_float4(0.f, 0.f, 0.f, 0.f);
        if (am < M) {
            int k = k0 + acol;
            if (k < K1) av = *reinterpret_cast<const float4*>(A1 + (size_t)am * K1 + k);
            else        av = *reinterpret_cast<const float4*>(A2 + (size_t)am * K2 + (k - K1));
        }
        float4 bv = *reinterpret_cast<const float4*>(W + (size_t)(k0 + bk) * NOUT + colBase + bn);

        __syncthreads();
        As[acol + 0][arow] = av.x;
        As[acol + 1][arow] = av.y;
        As[acol + 2][arow] = av.z;
        As[acol + 3][arow] = av.w;
        *reinterpret_cast<float4*>(&Bs[bk][bn]) = bv;
        __syncthreads();

#pragma unroll
        for (int kk = 0; kk < 8; kk++) {
            float a[8], b[8];
            *reinterpret_cast<float4*>(&a[0]) = *reinterpret_cast<const float4*>(&As[kk][ty * 8]);
            *reinterpret_cast<float4*>(&a[4]) = *reinterpret_cast<const float4*>(&As[kk][ty * 8 + 4]);
            *reinterpret_cast<float4*>(&b[0]) = *reinterpret_cast<const float4*>(&Bs[kk][tx * 8]);
            *reinterpret_cast<float4*>(&b[4]) = *reinterpret_cast<const float4*>(&Bs[kk][tx * 8 + 4]);
#pragma unroll
            for (int i = 0; i < 8; i++)
#pragma unroll
                for (int j = 0; j < 8; j++) acc[i][j] = fmaf(a[i], b[j], acc[i][j]);
        }
    }

    float bl[8];
#pragma unroll
    for (int j = 0; j < 8; j++) bl[j] = BIAS ? bias[colBase + tx * 8 + j] : 0.f;

#pragma unroll
    for (int i = 0; i < 8; i++) {
        int m = rowBase + ty * 8 + i;
        if (m >= M) continue;
        float r[8];
#pragma unroll
        for (int j = 0; j < 8; j++) {
            float x = acc[i][j] + bl[j];
            r[j] = SILU ? silu_f(x) : x;
        }
        float* cp = C + (size_t)m * NOUT + colBase + tx * 8;
        *reinterpret_cast<float4*>(cp)     = *reinterpret_cast<float4*>(&r[0]);
        *reinterpret_cast<float4*>(cp + 4) = *reinterpret_cast<float4*>(&r[4]);
    }
}

// ---------------------------------------------------------------------------
// Fused hull-edge kernel. Per block: 128 hull edges.
//   H   = silu(fea[128,16] @ W0 + b0)           (GEMM1, K=16, H kept in smem)
//   Wh  = H @ W1 + b1                           (GEMM2, K=128, BK=8 streamed)
//   e   = v_hull[j] * Wh ; red.add into acc[i]  (gather-multiply-scatter)
// Dynamic smem ~90KB -> 2 CTAs/SM.
// ---------------------------------------------------------------------------
__global__ __launch_bounds__(256, 2)
void hull_kernel(const float* __restrict__ fea, const int* __restrict__ jidx,
                 const int* __restrict__ iidx,
                 const float* __restrict__ W0, const float* __restrict__ b0,
                 const float* __restrict__ W1, const float* __restrict__ b1,
                 const float* __restrict__ vhull, float* __restrict__ accv, int EH) {
    extern __shared__ float sm[];
    float* sFeaT = sm;                  // [16][128] transposed fea tile
    float* sW0   = sFeaT + 16 * 128;    // [16][128]
    float* sH    = sW0 + 16 * 128;      // [128][132] (padded rows)
    float* sW1   = sH + 128 * 132;      // [8][128]
    float* sB0   = sW1 + 8 * 128;       // [128]
    float* sB1   = sB0 + 128;           // [128]
    int*   sJ    = (int*)(sB1 + 128);   // [128]
    int*   sI    = sJ + 128;            // [128]

    const int tid = threadIdx.x;
    const int tx = tid & 15;
    const int ty = tid >> 4;
    const int ebase = blockIdx.x * 128;

    // Load fea tile transposed: 512 float4, 2 per thread
#pragma unroll
    for (int q = 0; q < 2; q++) {
        int idx = tid * 2 + q;          // 0..511
        int row = idx >> 2;             // 0..127
        int kk = (idx & 3) * 4;         // 0,4,8,12
        int e = ebase + row;
        float4 f = make_float4(0.f, 0.f, 0.f, 0.f);
        if (e < EH) f = *reinterpret_cast<const float4*>(fea + (size_t)e * 16 + kk);
        sFeaT[(kk + 0) * 128 + row] = f.x;
        sFeaT[(kk + 1) * 128 + row] = f.y;
        sFeaT[(kk + 2) * 128 + row] = f.z;
        sFeaT[(kk + 3) * 128 + row] = f.w;
    }
    // Load W0 [16,128]
#pragma unroll
    for (int q = 0; q < 2; q++) {
        int idx = tid * 2 + q;          // 0..511
        int k = idx >> 5;               // 0..15
        int n = (idx & 31) * 4;
        *reinterpret_cast<float4*>(&sW0[k * 128 + n]) =
            *reinterpret_cast<const float4*>(W0 + (size_t)k * 128 + n);
    }
    if (tid < 128) {
        sB0[tid] = b0[tid];
        sB1[tid] = b1[tid];
        int e = ebase + tid;
        sJ[tid] = (e < EH) ? jidx[e] : 0;
        sI[tid] = (e < EH) ? iidx[e] : 0;
    }
    __syncthreads();

    float acc[8][8];
#pragma unroll
    for (int i = 0; i < 8; i++)
#pragma unroll
        for (int j = 0; j < 8; j++) acc[i][j] = 0.f;

    // GEMM1: K = 16
#pragma unroll
    for (int kk = 0; kk < 16; kk++) {
        float a[8], b[8];
        *reinterpret_cast<float4*>(&a[0]) = *reinterpret_cast<const float4*>(&sFeaT[kk * 128 + ty * 8]);
        *reinterpret_cast<float4*>(&a[4]) = *reinterpret_cast<const float4*>(&sFeaT[kk * 128 + ty * 8 + 4]);
        *reinterpret_cast<float4*>(&b[0]) = *reinterpret_cast<const float4*>(&sW0[kk * 128 + tx * 8]);
        *reinterpret_cast<float4*>(&b[4]) = *reinterpret_cast<const float4*>(&sW0[kk * 128 + tx * 8 + 4]);
#pragma unroll
        for (int i = 0; i < 8; i++)
#pragma unroll
            for (int j = 0; j < 8; j++) acc[i][j] = fmaf(a[i], b[j], acc[i][j]);
    }

    // SiLU + bias0 -> H (row-major, padded stride 132)
#pragma unroll
    for (int i = 0; i < 8; i++) {
        int row = ty * 8 + i;
        float r[8];
#pragma unroll
        for (int j = 0; j < 8; j++) r[j] = silu_f(acc[i][j] + sB0[tx * 8 + j]);
        *reinterpret_cast<float4*>(&sH[row * 132 + tx * 8])     = *reinterpret_cast<float4*>(&r[0]);
        *reinterpret_cast<float4*>(&sH[row * 132 + tx * 8 + 4]) = *reinterpret_cast<float4*>(&r[4]);
    }
    __syncthreads();

    // GEMM2: Wh = H @ W1, K = 128, BK = 8 streamed
#pragma unroll
    for (int i = 0; i < 8; i++)
#pragma unroll
        for (int j = 0; j < 8; j++) acc[i][j] = 0.f;

    for (int k0 = 0; k0 < 128; k0 += 8) {
        float4 wv = *reinterpret_cast<const float4*>(W1 + (size_t)(k0 + (tid >> 5)) * 128 + (tid & 31) * 4);
        __syncthreads();
        *reinterpret_cast<float4*>(&sW1[(tid >> 5) * 128 + (tid & 31) * 4]) = wv;
        __syncthreads();
#pragma unroll
        for (int kk = 0; kk < 8; kk++) {
            float a[8], b[8];
#pragma unroll
            for (int i = 0; i < 8; i++) a[i] = sH[(ty * 8 + i) * 132 + k0 + kk];
            *reinterpret_cast<float4*>(&b[0]) = *reinterpret_cast<const float4*>(&sW1[kk * 128 + tx * 8]);
            *reinterpret_cast<float4*>(&b[4]) = *reinterpret_cast<const float4*>(&sW1[kk * 128 + tx * 8 + 4]);
#pragma unroll
            for (int i = 0; i < 8; i++)
#pragma unroll
                for (int j = 0; j < 8; j++) acc[i][j] = fmaf(a[i], b[j], acc[i][j]);
        }
    }

    // Epilogue: bias1, multiply by gathered v_hull[j], vector-atomic scatter to acc[i]
    float bl[8];
#pragma unroll
    for (int j = 0; j < 8; j++) bl[j] = sB1[tx * 8 + j];

#pragma unroll
    for (int i = 0; i < 8; i++) {
        int e = ebase + ty * 8 + i;
        if (e >= EH) continue;
        int jn = sJ[ty * 8 + i];
        int in_ = sI[ty * 8 + i];
        const float* vr = vhull + (size_t)jn * 128 + tx * 8;
        float4 v0 = *reinterpret_cast<const float4*>(vr);
        float4 v1 = *reinterpret_cast<const float4*>(vr + 4);
        float4 r0, r1;
        r0.x = (acc[i][0] + bl[0]) * v0.x;
        r0.y = (acc[i][1] + bl[1]) * v0.y;
        r0.z = (acc[i][2] + bl[2]) * v0.z;
        r0.w = (acc[i][3] + bl[3]) * v0.w;
        r1.x = (acc[i][4] + bl[4]) * v1.x;
        r1.y = (acc[i][5] + bl[5]) * v1.y;
        r1.z = (acc[i][6] + bl[6]) * v1.z;
        r1.w = (acc[i][7] + bl[7]) * v1.w;
        float* op = accv + (size_t)in_ * 128 + tx * 8;
        red_add_v4(op, r0);
        red_add_v4(op + 4, r1);
    }
}

// ---------------------------------------------------------------------------
// Final projection: out[m] = dot(T[m, :256], w_out)   (one warp per row)
// ---------------------------------------------------------------------------
__global__ void dot_kernel(const float* __restrict__ T, const float* __restrict__ w,
                           float* __restrict__ out, int M) {
    int gw = (blockIdx.x * blockDim.x + threadIdx.x) >> 5;
    int lane = threadIdx.x & 31;
    if (gw >= M) return;
    const float4* row = reinterpret_cast<const float4*>(T + (size_t)gw * 256);
    const float4* wr  = reinterpret_cast<const float4*>(w);
    float4 a = row[lane];
    float4 b = row[lane + 32];
    float4 wa = __ldg(&wr[lane]);
    float4 wb = __ldg(&wr[lane + 32]);
    float s = a.x * wa.x + a.y * wa.y + a.z * wa.z + a.w * wa.w
            + b.x * wb.x + b.y * wb.y + b.z * wb.z + b.w * wb.w;
#pragma unroll
    for (int o = 16; o; o >>= 1) s += __shfl_down_sync(0xffffffffu, s, o);
    if (lane == 0) out[gw] = s;
}

// ---------------------------------------------------------------------------
// Launch
// ---------------------------------------------------------------------------
extern "C" void kernel_launch(void* const* d_in, const int* in_sizes, int n_in,
                              void* d_out, int out_size) {
    const float* e2      = (const float*)d_in[0];
    const int*   iidx    = (const int*)d_in[1];
    const float* fea     = (const float*)d_in[2];
    const int*   eih     = (const int*)d_in[3];    // [2, EH]: row0 = j_, row1 = i_
    const float* w_hull  = (const float*)d_in[4];
    const float* w_mlp0  = (const float*)d_in[5];
    const float* b_mlp0  = (const float*)d_in[6];
    const float* w_mlp1  = (const float*)d_in[7];
    const float* b_mlp1  = (const float*)d_in[8];
    const float* w1_hull = (const float*)d_in[9];
    const float* b1_hull = (const float*)d_in[10];
    const float* w2_hull = (const float*)d_in[11];
    const float* b2_hull = (const float*)d_in[12];
    const float* w_cat   = (const float*)d_in[13];
    const float* b_cat   = (const float*)d_in[14];
    const float* w_up    = (const float*)d_in[15];
    const float* b_up    = (const float*)d_in[16];
    const float* w_l0    = (const float*)d_in[17];
    const float* b_l0    = (const float*)d_in[18];
    const float* w_l1    = (const float*)d_in[19];
    const float* b_l1    = (const float*)d_in[20];
    const float* w_out   = (const float*)d_in[21];
    float* out = (float*)d_out;

    float *pv, *pvh, *pacc, *pb1, *pb2;
    cudaGetSymbolAddress((void**)&pv,   g_v);
    cudaGetSymbolAddress((void**)&pvh,  g_vhull);
    cudaGetSymbolAddress((void**)&pacc, g_acc);
    cudaGetSymbolAddress((void**)&pb1,  g_buf1);
    cudaGetSymbolAddress((void**)&pb2,  g_buf2);

    const int hull_smem = (16 * 128 + 16 * 128 + 128 * 132 + 8 * 128 + 128 + 128 + 128 + 128) * 4;
    cudaFuncSetAttribute(hull_kernel, cudaFuncAttributeMaxDynamicSharedMemorySize, hull_smem);

    // 0: zero v and the hull accumulator
    zero2_kernel<<<2048, 256>>>((float4*)pv, (float4*)pacc, NN * 128 / 4);

    // 1: v = segment_sum(e2, i)
    scatter_kernel<<<(EE * 32 + 255) / 256, 256>>>(e2, iidx, pv, EE);

    dim3 g1((NN + 127) / 128, 1);
    dim3 g2((NN + 127) / 128, 2);

    // 2: v_hull = v @ w_hull
    sgemm_kernel<false, false><<<g1, 256>>>(pv, 128, nullptr, 0, w_hull, nullptr, pvh, NN, 128);

    // 3: fused hull-edge MLP + gather-multiply + scatter-sum -> g_acc
    hull_kernel<<<(EHH + 127) / 128, 256, hull_smem>>>(
        fea, eih, eih + EHH, w_mlp0, b_mlp0, w_mlp1, b_mlp1, pvh, pacc, EHH);

    // 4: oh1 = silu(g_acc @ w1_hull + b1)          -> reuse g_vhull
    sgemm_kernel<true, true><<<g1, 256>>>(pacc, 128, nullptr, 0, w1_hull, b1_hull, pvh, NN, 128);

    // 5: oh2 = oh1 @ w2_hull + b2  [N,256]         -> g_buf1
    sgemm_kernel<true, false><<<g2, 256>>>(pvh, 128, nullptr, 0, w2_hull, b2_hull, pb1, NN, 256);

    // 6: v2 = silu(concat(v, oh2) @ w_cat + b)     -> reuse g_acc (split-A GEMM, K=128+256)
    sgemm_kernel<true, true><<<g1, 256>>>(pv, 128, pb1, 256, w_cat, b_cat, pacc, NN, 128);

    // 7: t = v2 @ w_up + b                          -> g_buf2
    sgemm_kernel<true, false><<<g2, 256>>>(pacc, 128, nullptr, 0, w_up, b_up, pb2, NN, 256);

    // 8: t = silu(t @ w_l0 + b)                     -> g_buf1
    sgemm_kernel<true, true><<<g2, 256>>>(pb2, 256, nullptr, 0, w_l0, b_l0, pb1, NN, 256);

    // 9: t = silu(t @ w_l1 + b)                     -> g_buf2
    sgemm_kernel<true, true><<<g2, 256>>>(pb1, 256, nullptr, 0, w_l1, b_l1, pb2, NN, 256);

    // 10: out = t @ w_out
    dot_kernel<<<(NN * 32 + 255) / 256, 256>>>(pb2, w_out, out, NN);
}